// round 4
// baseline (speedup 1.0000x reference)
#include <cuda_runtime.h>
#include <cuda_bf16.h>

#define NCLS 10
#define DIM  128
#define WARPS_PER_BLOCK 4
#define BLOCK_THREADS   (WARPS_PER_BLOCK * 32)
#define GRID_BLOCKS     740   // 148 SMs * 5 blocks (smem-limited occupancy)

// Global scratch (allocation-free): per-(class,feature) sum and sum-of-squares,
// per-class counts. Zeroed every launch by zero_kernel so graph replay is
// deterministic.
__device__ float        g_sum[NCLS * DIM];
__device__ float        g_sq [NCLS * DIM];
__device__ unsigned int g_cnt[NCLS];

__global__ void CLIR_zero_kernel() {
    int i = blockIdx.x * blockDim.x + threadIdx.x;
    if (i < NCLS * DIM) { g_sum[i] = 0.0f; g_sq[i] = 0.0f; }
    if (i < NCLS) g_cnt[i] = 0u;
}

// One warp processes one row per iteration: 32 lanes x float4 = 128 floats
// = the full 512B row, perfectly coalesced. Each warp owns a PRIVATE shared
// accumulator copy, so the class-indexed read-modify-write needs no atomics
// and has no cross-warp races. Lane l exclusively owns columns 4l..4l+3.
__global__ __launch_bounds__(BLOCK_THREADS)
void CLIR_accum_kernel(const float* __restrict__ x,
                       const int*   __restrict__ t,
                       int N) {
    __shared__ float s_sum[WARPS_PER_BLOCK][NCLS * DIM];   // 20 KB
    __shared__ float s_sq [WARPS_PER_BLOCK][NCLS * DIM];   // 20 KB
    __shared__ unsigned int s_cnt[NCLS];

    const int tid  = threadIdx.x;
    const int lane = tid & 31;
    const int w    = tid >> 5;

    // Zero shared accumulators.
    float* s_sum_flat = &s_sum[0][0];
    float* s_sq_flat  = &s_sq[0][0];
    for (int i = tid; i < WARPS_PER_BLOCK * NCLS * DIM; i += BLOCK_THREADS) {
        s_sum_flat[i] = 0.0f;
        s_sq_flat[i]  = 0.0f;
    }
    if (tid < NCLS) s_cnt[tid] = 0u;
    __syncthreads();

    float* ms = s_sum[w];
    float* mq = s_sq[w];
    const float4* __restrict__ x4 = (const float4*)x;

    for (int row = blockIdx.x * WARPS_PER_BLOCK + w; row < N;
         row += GRID_BLOCKS * WARPS_PER_BLOCK) {
        const int c = __ldg(&t[row]);                       // warp-uniform broadcast
        const float4 v = x4[(size_t)row * (DIM / 4) + lane]; // 512B/warp coalesced

        float4* ps = (float4*)(ms + c * DIM + lane * 4);
        float4* pq = (float4*)(mq + c * DIM + lane * 4);
        float4 a = *ps;
        float4 b = *pq;
        a.x += v.x; a.y += v.y; a.z += v.z; a.w += v.w;
        b.x = fmaf(v.x, v.x, b.x);
        b.y = fmaf(v.y, v.y, b.y);
        b.z = fmaf(v.z, v.z, b.z);
        b.w = fmaf(v.w, v.w, b.w);
        *ps = a;
        *pq = b;

        if (lane == 0) atomicAdd(&s_cnt[c], 1u);
    }
    __syncthreads();

    // Fold the 4 warp-copies and push to global via spread float atomics
    // (~2560 atomics/block over 10240 distinct addresses chip-wide).
    for (int i = tid; i < NCLS * DIM; i += BLOCK_THREADS) {
        float vs = s_sum[0][i] + s_sum[1][i] + s_sum[2][i] + s_sum[3][i];
        float vq = s_sq[0][i]  + s_sq[1][i]  + s_sq[2][i]  + s_sq[3][i];
        atomicAdd(&g_sum[i], vs);
        atomicAdd(&g_sq[i],  vq);
    }
    if (tid < NCLS) atomicAdd(&g_cnt[tid], s_cnt[tid]);
}

// Single block: thread d handles feature d for all classes, then block-reduce.
// trace_c = sum_d ( SumSq[c][d] - Sum[c][d]^2 / n_c ), result = (1/C) *
// sum_c trace_c / (n_c - 1).
__global__ void CLIR_finalize_kernel(float* __restrict__ out) {
    const int d = threadIdx.x;   // 128 threads
    float acc = 0.0f;
    #pragma unroll
    for (int c = 0; c < NCLS; c++) {
        const float n = (float)g_cnt[c];
        const float s = g_sum[c * DIM + d];
        const float q = g_sq [c * DIM + d];
        acc += (q - s * s / n) / (n - 1.0f);
    }
    #pragma unroll
    for (int o = 16; o > 0; o >>= 1)
        acc += __shfl_xor_sync(0xFFFFFFFFu, acc, o);
    __shared__ float wr[4];
    if ((d & 31) == 0) wr[d >> 5] = acc;
    __syncthreads();
    if (d == 0)
        out[0] = (wr[0] + wr[1] + wr[2] + wr[3]) * (1.0f / (float)NCLS);
}

extern "C" void kernel_launch(void* const* d_in, const int* in_sizes, int n_in,
                              void* d_out, int out_size) {
    const float* x = (const float*)d_in[0];
    const int*   t = (const int*)d_in[1];
    const int N = in_sizes[1];          // label count; x has N*DIM elements

    CLIR_zero_kernel<<<(NCLS * DIM + 255) / 256, 256>>>();
    CLIR_accum_kernel<<<GRID_BLOCKS, BLOCK_THREADS>>>(x, t, N);
    CLIR_finalize_kernel<<<1, DIM>>>((float*)d_out);
}